// round 2
// baseline (speedup 1.0000x reference)
#include <cuda_runtime.h>
#include <math.h>

#define NB      4
#define D_MODEL 256
#define HEADS   4
#define HEAD_DIM 64
#define NPTS    4096
#define TWO_D   512
#define L2E     1.4426950408889634f

// ---------------- scratch (device globals; no allocations allowed) ----------
__device__ float g_Q[NB * D_MODEL * NPTS];
__device__ float g_K[NB * D_MODEL * NPTS];
__device__ float g_V[NB * D_MODEL * NPTS];
__device__ float g_attn[NB * D_MODEL * NPTS];
__device__ float g_msg[NB * D_MODEL * NPTS];
__device__ float g_h[NB * TWO_D * NPTS];
__device__ float g_mean[TWO_D];
__device__ float g_istd[TWO_D];

// ---------------------------------------------------------------------------
// Generic conv1 (1x1 conv == per-position GEMM):
//   out[b][o][n] = bias[o] + sum_{c<Ca} W[o][c]*A[b][c][n]
//                          + sum_{c}    W[o][Ca+c]*B2[b][c][n]
// Block computes a 64(o) x 64(n) tile, 256 threads, 4x4 micro-tile, K-tile 16.
// ---------------------------------------------------------------------------
__global__ void __launch_bounds__(256) gemm_conv1(
    const float* __restrict__ A, const float* __restrict__ B2,
    const float* __restrict__ W, const float* __restrict__ bias,
    float* __restrict__ out, int Ca, int Cb, int O)
{
    __shared__ float Ws[16][68];   // [kk][oo], stride 68 => conflict-light
    __shared__ float Xs[16][64];   // [kk][nn], float4 reads conflict-free

    const int b  = blockIdx.z;
    const int o0 = blockIdx.y * 64;
    const int n0 = blockIdx.x * 64;
    const int t  = threadIdx.x;
    const int tx = t & 15;         // n-group
    const int ty = t >> 4;         // o-group
    const int C  = Ca + Cb;

    const float* Abase = A + (size_t)b * Ca * NPTS + n0;
    const float* Bbase = (Cb > 0) ? (B2 + (size_t)b * Cb * NPTS + n0) : nullptr;

    float acc[4][4];
#pragma unroll
    for (int i = 0; i < 4; i++)
#pragma unroll
        for (int j = 0; j < 4; j++) acc[i][j] = 0.f;

    for (int k0 = 0; k0 < C; k0 += 16) {
        // load W tile: 64 o x 16 k
#pragma unroll
        for (int r = 0; r < 4; r++) {
            int idx = t + r * 256;
            int kk = idx & 15, oo = idx >> 4;
            Ws[kk][oo] = W[(size_t)(o0 + oo) * C + (k0 + kk)];
        }
        // load X tile: 16 k x 64 n (concat-aware)
#pragma unroll
        for (int r = 0; r < 4; r++) {
            int idx = t + r * 256;
            int nn = idx & 63, kk = idx >> 6;
            int c = k0 + kk;
            float v = (c < Ca) ? Abase[(size_t)c * NPTS + nn]
                               : Bbase[(size_t)(c - Ca) * NPTS + nn];
            Xs[kk][nn] = v;
        }
        __syncthreads();

#pragma unroll
        for (int kk = 0; kk < 16; kk++) {
            float4 a4 = *(const float4*)&Ws[kk][ty * 4];
            float4 b4 = *(const float4*)&Xs[kk][tx * 4];
            float av[4] = {a4.x, a4.y, a4.z, a4.w};
            float bv[4] = {b4.x, b4.y, b4.z, b4.w};
#pragma unroll
            for (int i = 0; i < 4; i++)
#pragma unroll
                for (int j = 0; j < 4; j++) acc[i][j] = fmaf(av[i], bv[j], acc[i][j]);
        }
        __syncthreads();
    }

#pragma unroll
    for (int i = 0; i < 4; i++) {
        float bs = bias[o0 + ty * 4 + i];
        float4 r;
        r.x = acc[i][0] + bs; r.y = acc[i][1] + bs;
        r.z = acc[i][2] + bs; r.w = acc[i][3] + bs;
        *(float4*)&out[((size_t)b * O + o0 + ty * 4 + i) * NPTS + n0 + tx * 4] = r;
    }
}

// ---------------------------------------------------------------------------
// Flash attention, fp32. One block per (b, h, 64-row n-tile). 256 threads.
// head channel mapping: full-channel c = d*HEADS + h (torch view(B,dim,h,-1)).
// Online softmax over 64-wide m tiles; Q pre-scaled by 1/sqrt(64).
// ---------------------------------------------------------------------------
#define FA_SMEM_FLOATS (64*64 + 64*68 + 64*68 + 64*65)
#define FA_SMEM_BYTES  (FA_SMEM_FLOATS * 4)

extern __shared__ float fa_smem[];

__global__ void __launch_bounds__(256) flash_attn_kernel(
    const float* __restrict__ Q, const float* __restrict__ K,
    const float* __restrict__ V, float* __restrict__ Out)
{
    float* Qs = fa_smem;            // [dd][nn], stride 64 (reads are ty-broadcast)
    float* Ks = Qs + 64 * 64;       // [dd][mm], stride 68 (float4 CF)
    float* Vs = Ks + 64 * 68;       // [mm][dd], stride 68 (float4 CF)
    float* Ps = Vs + 64 * 68;       // [mm][nn], stride 65 (scalar broadcast reads)

    const int n0 = blockIdx.x * 64;
    const int h  = blockIdx.y;
    const int b  = blockIdx.z;
    const int t  = threadIdx.x;
    const int tx = t & 15;          // m-group (S) / d-group (O)
    const int ty = t >> 4;          // n-group

    const float* Qb = Q + (size_t)b * D_MODEL * NPTS;
    const float* Kb = K + (size_t)b * D_MODEL * NPTS;
    const float* Vb = V + (size_t)b * D_MODEL * NPTS;

    // load Q tile (scaled)
    {
        int nn = t & 63, d0 = t >> 6;
        for (int dd = d0; dd < 64; dd += 4)
            Qs[dd * 64 + nn] = Qb[(size_t)(dd * HEADS + h) * NPTS + n0 + nn] * 0.125f;
    }

    float m_run[4], l_run[4], acc[4][4];
#pragma unroll
    for (int i = 0; i < 4; i++) {
        m_run[i] = -INFINITY; l_run[i] = 0.f;
#pragma unroll
        for (int j = 0; j < 4; j++) acc[i][j] = 0.f;
    }
    __syncthreads();

    for (int m0 = 0; m0 < NPTS; m0 += 64) {
        // load K [dd][mm] and V transposed [mm][dd]
        {
            int mm = t & 63, d0 = t >> 6;
            for (int dd = d0; dd < 64; dd += 4) {
                float kv = Kb[(size_t)(dd * HEADS + h) * NPTS + m0 + mm];
                float vv = Vb[(size_t)(dd * HEADS + h) * NPTS + m0 + mm];
                Ks[dd * 68 + mm] = kv;
                Vs[mm * 68 + dd] = vv;
            }
        }
        __syncthreads();

        // S = Qs^T Ks  (4x4 per thread)
        float S[4][4];
#pragma unroll
        for (int i = 0; i < 4; i++)
#pragma unroll
            for (int j = 0; j < 4; j++) S[i][j] = 0.f;

#pragma unroll 8
        for (int dd = 0; dd < 64; dd++) {
            float4 a4 = *(const float4*)&Qs[dd * 64 + ty * 4];
            float4 b4 = *(const float4*)&Ks[dd * 68 + tx * 4];
            float av[4] = {a4.x, a4.y, a4.z, a4.w};
            float bv[4] = {b4.x, b4.y, b4.z, b4.w};
#pragma unroll
            for (int i = 0; i < 4; i++)
#pragma unroll
                for (int j = 0; j < 4; j++) S[i][j] = fmaf(av[i], bv[j], S[i][j]);
        }

        // row-wise online softmax (reduce across the 16 tx lanes)
        float m_new[4], alpha[4], rsum[4];
#pragma unroll
        for (int i = 0; i < 4; i++) {
            float rmax = fmaxf(fmaxf(S[i][0], S[i][1]), fmaxf(S[i][2], S[i][3]));
#pragma unroll
            for (int off = 8; off > 0; off >>= 1)
                rmax = fmaxf(rmax, __shfl_xor_sync(0xffffffffu, rmax, off));
            m_new[i] = fmaxf(m_run[i], rmax);
            alpha[i] = exp2f((m_run[i] - m_new[i]) * L2E);
            float rs = 0.f;
#pragma unroll
            for (int j = 0; j < 4; j++) {
                S[i][j] = exp2f((S[i][j] - m_new[i]) * L2E);
                rs += S[i][j];
            }
#pragma unroll
            for (int off = 8; off > 0; off >>= 1)
                rs += __shfl_xor_sync(0xffffffffu, rs, off);
            rsum[i] = rs;
        }
#pragma unroll
        for (int i = 0; i < 4; i++) {
            l_run[i] = l_run[i] * alpha[i] + rsum[i];
            m_run[i] = m_new[i];
#pragma unroll
            for (int j = 0; j < 4; j++) acc[i][j] *= alpha[i];
        }

        // stash P transposed: Ps[m][n]
#pragma unroll
        for (int j = 0; j < 4; j++)
#pragma unroll
            for (int i = 0; i < 4; i++)
                Ps[(tx * 4 + j) * 65 + ty * 4 + i] = S[i][j];
        __syncthreads();

        // O += P * V   (acc[n_i][d_j])
#pragma unroll 4
        for (int mm = 0; mm < 64; mm++) {
            float av[4];
#pragma unroll
            for (int i = 0; i < 4; i++) av[i] = Ps[mm * 65 + ty * 4 + i];
            float4 b4 = *(const float4*)&Vs[mm * 68 + tx * 4];
            float bv[4] = {b4.x, b4.y, b4.z, b4.w};
#pragma unroll
            for (int i = 0; i < 4; i++)
#pragma unroll
                for (int j = 0; j < 4; j++) acc[i][j] = fmaf(av[i], bv[j], acc[i][j]);
        }
        __syncthreads();
    }

    // epilogue: normalize, scatter to attn_out with c = d*HEADS + h
#pragma unroll
    for (int i = 0; i < 4; i++) {
        float inv = 1.f / l_run[i];
#pragma unroll
        for (int j = 0; j < 4; j++) {
            int d = tx * 4 + j;
            Out[((size_t)b * D_MODEL + d * HEADS + h) * NPTS + n0 + ty * 4 + i] =
                acc[i][j] * inv;
        }
    }
}

// ---------------------------------------------------------------------------
// BatchNorm (training-mode batch stats over axes (B, N)), biased variance.
// One block per channel -> fully deterministic (no atomics).
// ---------------------------------------------------------------------------
__global__ void __launch_bounds__(256) bn_stats_kernel(
    const float* __restrict__ hbuf, float* __restrict__ meanp, float* __restrict__ istdp)
{
    const int c = blockIdx.x;
    float s = 0.f, s2 = 0.f;
    for (int idx = threadIdx.x; idx < NB * NPTS; idx += 256) {
        int b = idx >> 12;
        int n = idx & (NPTS - 1);
        float v = hbuf[((size_t)b * TWO_D + c) * NPTS + n];
        s += v; s2 += v * v;
    }
    __shared__ float sh[256], sh2[256];
    sh[threadIdx.x] = s; sh2[threadIdx.x] = s2;
    __syncthreads();
    for (int st = 128; st > 0; st >>= 1) {
        if (threadIdx.x < st) {
            sh[threadIdx.x]  += sh[threadIdx.x + st];
            sh2[threadIdx.x] += sh2[threadIdx.x + st];
        }
        __syncthreads();
    }
    if (threadIdx.x == 0) {
        const float invn = 1.f / (float)(NB * NPTS);
        float mean = sh[0] * invn;
        float var  = sh2[0] * invn - mean * mean;
        meanp[c] = mean;
        istdp[c] = rsqrtf(var + 1e-5f);
    }
}

__global__ void __launch_bounds__(256) bn_apply_relu_kernel(
    float* __restrict__ hbuf, const float* __restrict__ gamma,
    const float* __restrict__ beta, const float* __restrict__ meanp,
    const float* __restrict__ istdp)
{
    size_t i4 = (size_t)blockIdx.x * 256 + threadIdx.x;   // float4 index
    size_t e  = i4 * 4;
    int c = (int)((e >> 12) & (TWO_D - 1));               // (e/4096) % 512
    float mu = meanp[c], is = istdp[c], ga = gamma[c], be = beta[c];
    float4 v = ((float4*)hbuf)[i4];
    v.x = fmaxf(fmaf((v.x - mu) * is, ga, be), 0.f);
    v.y = fmaxf(fmaf((v.y - mu) * is, ga, be), 0.f);
    v.z = fmaxf(fmaf((v.z - mu) * is, ga, be), 0.f);
    v.w = fmaxf(fmaf((v.w - mu) * is, ga, be), 0.f);
    ((float4*)hbuf)[i4] = v;
}

// ---------------------------------------------------------------------------
extern "C" void kernel_launch(void* const* d_in, const int* in_sizes, int n_in,
                              void* d_out, int out_size)
{
    (void)in_sizes; (void)n_in; (void)out_size;

    const float* x       = (const float*)d_in[0];
    const float* src     = (const float*)d_in[1];
    const float* pq_w    = (const float*)d_in[2];
    const float* pq_b    = (const float*)d_in[3];
    const float* pk_w    = (const float*)d_in[4];
    const float* pk_b    = (const float*)d_in[5];
    const float* pv_w    = (const float*)d_in[6];
    const float* pv_b    = (const float*)d_in[7];
    const float* merge_w = (const float*)d_in[8];
    const float* merge_b = (const float*)d_in[9];
    const float* mlp1_w  = (const float*)d_in[10];
    const float* mlp1_b  = (const float*)d_in[11];
    const float* bn_g    = (const float*)d_in[12];
    const float* bn_b    = (const float*)d_in[13];
    const float* mlp2_w  = (const float*)d_in[14];
    const float* mlp2_b  = (const float*)d_in[15];
    float* out = (float*)d_out;

    float *Qp, *Kp, *Vp, *Ap, *Mp, *Hp, *meanp, *istdp;
    cudaGetSymbolAddress((void**)&Qp,    g_Q);
    cudaGetSymbolAddress((void**)&Kp,    g_K);
    cudaGetSymbolAddress((void**)&Vp,    g_V);
    cudaGetSymbolAddress((void**)&Ap,    g_attn);
    cudaGetSymbolAddress((void**)&Mp,    g_msg);
    cudaGetSymbolAddress((void**)&Hp,    g_h);
    cudaGetSymbolAddress((void**)&meanp, g_mean);
    cudaGetSymbolAddress((void**)&istdp, g_istd);

    cudaFuncSetAttribute(flash_attn_kernel,
                         cudaFuncAttributeMaxDynamicSharedMemorySize, FA_SMEM_BYTES);

    dim3 blk(256);

    // Q/K/V projections
    gemm_conv1<<<dim3(NPTS/64, D_MODEL/64, NB), blk>>>(x,   nullptr, pq_w, pq_b, Qp, D_MODEL, 0, D_MODEL);
    gemm_conv1<<<dim3(NPTS/64, D_MODEL/64, NB), blk>>>(src, nullptr, pk_w, pk_b, Kp, D_MODEL, 0, D_MODEL);
    gemm_conv1<<<dim3(NPTS/64, D_MODEL/64, NB), blk>>>(src, nullptr, pv_w, pv_b, Vp, D_MODEL, 0, D_MODEL);

    // multi-head attention (flash style)
    flash_attn_kernel<<<dim3(NPTS/64, HEADS, NB), blk, FA_SMEM_BYTES>>>(Qp, Kp, Vp, Ap);

    // merge
    gemm_conv1<<<dim3(NPTS/64, D_MODEL/64, NB), blk>>>(Ap, nullptr, merge_w, merge_b, Mp, D_MODEL, 0, D_MODEL);

    // mlp1 on concat([x, message])
    gemm_conv1<<<dim3(NPTS/64, TWO_D/64, NB), blk>>>(x, Mp, mlp1_w, mlp1_b, Hp, D_MODEL, D_MODEL, TWO_D);

    // BatchNorm (batch stats) + ReLU
    bn_stats_kernel<<<TWO_D, 256>>>(Hp, meanp, istdp);
    bn_apply_relu_kernel<<<(NB * TWO_D * NPTS / 4) / 256, 256>>>(Hp, bn_g, bn_b, meanp, istdp);

    // mlp2 -> output
    gemm_conv1<<<dim3(NPTS/64, D_MODEL/64, NB), blk>>>(Hp, nullptr, mlp2_w, mlp2_b, out, TWO_D, 0, D_MODEL);
}